// round 1
// baseline (speedup 1.0000x reference)
#include <cuda_runtime.h>

#define BB 64
#define NN 512
#define EPS 1e-10f

// Scratch (allocation-free rule: __device__ globals)
__device__ float4 g_items[BB * NN];   // {gain, disc, exp(score), 0}
__device__ float  g_rowScale[BB];     // ln2 / (idcg * (cnt+eps)) / B
__device__ float  g_rowSum[BB];

// ---------------- Kernel 1: per-item precompute, per-row constants -------------
__global__ void lr_prep(const float* __restrict__ scores,
                        const float* __restrict__ relevance) {
    const int row = blockIdx.x;
    const int t   = threadIdx.x;

    __shared__ float ss[NN];
    __shared__ int   counts[5];
    __shared__ float red[NN];

    float si = scores[row * NN + t];
    int   r  = (int)relevance[row * NN + t];
    ss[t] = si;
    if (t < 5) counts[t] = 0;
    __syncthreads();
    atomicAdd(&counts[r], 1);

    // predicted rank (1-based, stable tie-break by index, descending scores)
    int rk = 1;
    #pragma unroll 8
    for (int j = 0; j < NN; ++j) {
        float sj = ss[j];
        rk += (sj > si) || (sj == si && j < t);
    }
    float d = __fdividef(1.0f, __log2f((float)(rk + 2)));
    float g = (float)((1 << r) - 1);
    float E = __expf(si);
    g_items[row * NN + t] = make_float4(g, d, E, 0.0f);

    __syncthreads();  // counts ready
    int c4 = counts[4], c3 = counts[3], c2 = counts[2], c1 = counts[1];
    int b4 = c4, b3 = b4 + c3, b2 = b3 + c2, b1 = b2 + c1;

    // ideal DCG: position t holds the t-th highest relevance
    float gl = t < b4 ? 15.f : t < b3 ? 7.f : t < b2 ? 3.f : t < b1 ? 1.f : 0.f;
    red[t] = __fdividef(gl, __log2f((float)(t + 2)));
    __syncthreads();
    for (int s = NN / 2; s > 0; s >>= 1) {
        if (t < s) red[t] += red[t + s];
        __syncthreads();
    }
    if (t == 0) {
        float idcg = fmaxf(red[0], EPS);
        int c0 = NN - (c4 + c3 + c2 + c1);
        long long sq = (long long)c4 * c4 + (long long)c3 * c3 +
                       (long long)c2 * c2 + (long long)c1 * c1 +
                       (long long)c0 * c0;
        float cnt = 0.5f * (float)((long long)NN * NN - sq);
        g_rowScale[row] = 0.6931471805599453f /
                          (idcg * (cnt + EPS)) / (float)BB;
        g_rowSum[row] = 0.0f;
    }
}

// ---------------- Kernel 2: pairwise accumulation -----------------------------
// grid (8, 64), 64 threads. Each thread owns i = blockIdx.x*64 + tid, loops all j.
__global__ void lr_pairs() {
    __shared__ float4 sj[NN];
    const int row = blockIdx.y;
    const int tid = threadIdx.x;

    const float4* items = g_items + row * NN;
    for (int k = tid; k < NN; k += blockDim.x) sj[k] = items[k];
    __syncthreads();

    const int i = blockIdx.x * 64 + tid;
    float4 mi = sj[i];
    float gi = mi.x, di = mi.y;
    float Einv = __fdividef(1.0f, mi.z);  // exp(-s_i)

    float acc = 0.0f;
    #pragma unroll 8
    for (int j = 0; j < NN; ++j) {
        float4 mj = sj[j];
        float w  = fmaxf(gi - mj.x, 0.0f);     // validity folded into gain diff
        float dd = fabsf(di - mj.y);
        float u  = Einv * mj.z;                // exp(-(s_i - s_j))
        float lg = __log2f(1.0f + u);          // ln2 applied in rowScale
        acc = fmaf(w * dd, lg, acc);
    }

    #pragma unroll
    for (int o = 16; o > 0; o >>= 1) acc += __shfl_down_sync(0xffffffffu, acc, o);
    __shared__ float wsum[2];
    if ((tid & 31) == 0) wsum[tid >> 5] = acc;
    __syncthreads();
    if (tid == 0) atomicAdd(&g_rowSum[row], wsum[0] + wsum[1]);
}

// ---------------- Kernel 3: final reduce over rows ----------------------------
__global__ void lr_final(float* __restrict__ out) {
    const int t = threadIdx.x;
    float v = g_rowSum[t] * g_rowScale[t];
    #pragma unroll
    for (int o = 16; o > 0; o >>= 1) v += __shfl_down_sync(0xffffffffu, v, o);
    __shared__ float w[2];
    if ((t & 31) == 0) w[t >> 5] = v;
    __syncthreads();
    if (t == 0) out[0] = w[0] + w[1];
}

extern "C" void kernel_launch(void* const* d_in, const int* in_sizes, int n_in,
                              void* d_out, int out_size) {
    const float* scores    = (const float*)d_in[0];
    const float* relevance = (const float*)d_in[1];
    float* out = (float*)d_out;

    lr_prep<<<BB, NN>>>(scores, relevance);
    lr_pairs<<<dim3(8, BB), 64>>>();
    lr_final<<<1, BB>>>(out);
}

// round 2
// speedup vs baseline: 1.0898x; 1.0898x over previous
#include <cuda_runtime.h>

#define BB 64
#define NN 512
#define EPS 1e-10f
#define L2E 1.4426950408889634f   // log2(e)

// Scratch (allocation-free rule: __device__ globals)
__device__ float4   g_items[BB * NN];   // {gain, disc, exp(score), score}
__device__ float    g_rowScale[BB];     // ln2 / (idcg * (cnt+eps)) / B
__device__ float    g_accum = 0.0f;
__device__ unsigned g_count = 0u;

// ---------------- Kernel 1: per-item precompute, per-row constants -------------
// grid (4, 64), 512 threads. Block (q,row) computes items i in [q*128, q*128+128):
// 4 threads per item, each scanning 128 j's; quad-reduce via shfl.
__global__ void lr_prep(const float* __restrict__ scores,
                        const float* __restrict__ relevance) {
    const int q   = blockIdx.x;
    const int row = blockIdx.y;
    const int t   = threadIdx.x;

    __shared__ float ss[NN];
    __shared__ int   sr[NN];
    __shared__ int   counts[5];
    __shared__ float wred[16];

    float sv = scores[row * NN + t];
    int   rv = (int)relevance[row * NN + t];
    ss[t] = sv;
    sr[t] = rv;
    if (q == 0 && t < 5) counts[t] = 0;
    __syncthreads();

    // partial predicted rank (1-based, stable tie-break by index)
    const int i_loc = t >> 2;
    const int part  = t & 3;
    const int i     = q * 128 + i_loc;
    const float si  = ss[i];
    int cnt = 0;
    const int j0 = part * 128;
    #pragma unroll 8
    for (int jj = 0; jj < 128; ++jj) {
        int j = j0 + jj;
        float sj = ss[j];
        cnt += (sj > si) || (sj == si && j < i);
    }
    cnt += __shfl_down_sync(0xffffffffu, cnt, 2, 4);
    cnt += __shfl_down_sync(0xffffffffu, cnt, 1, 4);

    if (part == 0) {
        int rank = cnt + 1;
        int r = sr[i];
        float g = (float)((1 << r) - 1);
        float d = __fdividef(1.0f, __log2f((float)(rank + 2)));
        g_items[row * NN + i] = make_float4(g, d, __expf(si), si);
    }

    // Row constants: only block q==0 (branch uniform within block).
    if (q == 0) {
        atomicAdd(&counts[rv], 1);
        __syncthreads();
        int c4 = counts[4], c3 = counts[3], c2 = counts[2], c1 = counts[1];
        int b4 = c4, b3 = b4 + c3, b2 = b3 + c2, b1 = b2 + c1;

        // ideal DCG: position t holds the t-th highest relevance
        float gl = t < b4 ? 15.f : t < b3 ? 7.f : t < b2 ? 3.f : t < b1 ? 1.f : 0.f;
        float v = __fdividef(gl, __log2f((float)(t + 2)));
        #pragma unroll
        for (int o = 16; o > 0; o >>= 1) v += __shfl_down_sync(0xffffffffu, v, o);
        if ((t & 31) == 0) wred[t >> 5] = v;
        __syncthreads();
        if (t < 32) {
            float v2 = (t < 16) ? wred[t] : 0.0f;
            #pragma unroll
            for (int o = 16; o > 0; o >>= 1) v2 += __shfl_down_sync(0xffffffffu, v2, o);
            if (t == 0) {
                float idcg = fmaxf(v2, EPS);
                int c0 = NN - (c4 + c3 + c2 + c1);
                float sq = (float)c4 * c4 + (float)c3 * c3 + (float)c2 * c2 +
                           (float)c1 * c1 + (float)c0 * c0;
                float cntf = 0.5f * ((float)NN * NN - sq);
                g_rowScale[row] = 0.6931471805599453f /
                                  (idcg * (cntf + EPS)) / (float)BB;
            }
        }
    }
}

// ---------------- Kernel 2: pairwise over unordered pairs ----------------------
// grid (4, 64), 128 threads. Thread owns i = bx*128+tid; round-robin half loop
// covers each unordered pair exactly once; both directions share one log2.
__global__ void lr_pairs(float* __restrict__ out) {
    __shared__ float4 sj[2 * NN];   // doubled to avoid (i+k)&511 in inner loop
    const int row = blockIdx.y;
    const int tid = threadIdx.x;

    const float4* items = g_items + row * NN;
    for (int k = tid; k < NN; k += 128) {
        float4 v = items[k];
        sj[k] = v;
        sj[k + NN] = v;
    }
    __syncthreads();

    const int i = blockIdx.x * 128 + tid;
    const float4 mi = sj[i];
    const float gi = mi.x, di = mi.y, si = mi.w;
    const float Einv = __fdividef(1.0f, mi.z);   // exp(-s_i)

    float acc = 0.0f;
    #pragma unroll 8
    for (int k = 1; k < 256; ++k) {
        float4 mj = sj[i + k];
        float dg  = gi - mj.x;                   // >0: i wins, <0: j wins
        float dd  = fabsf(di - mj.y);
        float u   = Einv * mj.z;                 // exp(s_j - s_i)
        float lg  = __log2f(1.0f + u);           // softplus(s_i-s_j)/ln2
        float alt = fmaf(si - mj.w, L2E, lg);    // softplus(s_j-s_i)/ln2
        float sel = (dg > 0.0f) ? lg : alt;
        acc = fmaf(fabsf(dg) * dd, sel, acc);
    }
    // distance-256 pairs: each appears for both endpoints; count once (bx<2 uniform)
    if (i < 256) {
        float4 mj = sj[i + 256];
        float dg  = gi - mj.x;
        float dd  = fabsf(di - mj.y);
        float u   = Einv * mj.z;
        float lg  = __log2f(1.0f + u);
        float alt = fmaf(si - mj.w, L2E, lg);
        float sel = (dg > 0.0f) ? lg : alt;
        acc = fmaf(fabsf(dg) * dd, sel, acc);
    }

    // block reduce (4 warps)
    #pragma unroll
    for (int o = 16; o > 0; o >>= 1) acc += __shfl_down_sync(0xffffffffu, acc, o);
    __shared__ float ws[4];
    if ((tid & 31) == 0) ws[tid >> 5] = acc;
    __syncthreads();
    if (tid == 0) {
        float bs = (ws[0] + ws[1] + ws[2] + ws[3]) * g_rowScale[row];
        atomicAdd(&g_accum, bs);
        __threadfence();
        unsigned n = atomicAdd(&g_count, 1u);
        if (n == 4u * BB - 1u) {                 // last block finalizes
            float total = atomicAdd(&g_accum, 0.0f);
            out[0] = total;
            g_accum = 0.0f;                      // reset for next graph replay
            g_count = 0u;
        }
    }
}

extern "C" void kernel_launch(void* const* d_in, const int* in_sizes, int n_in,
                              void* d_out, int out_size) {
    const float* scores    = (const float*)d_in[0];
    const float* relevance = (const float*)d_in[1];
    float* out = (float*)d_out;

    lr_prep<<<dim3(4, BB), NN>>>(scores, relevance);
    lr_pairs<<<dim3(4, BB), 128>>>(out);
}